// round 11
// baseline (speedup 1.0000x reference)
#include <cuda_runtime.h>
#include <cuda_fp16.h>
#include <cstdint>
#include <cstddef>

// Problem constants (fixed by the dataset)
#define NU_MAX 100000
#define NI_MAX 50000
#define E_MAX 300000
#define DD 128
#define SCAN_B 1024

// ---------------- device scratch (no allocations allowed) ----------------
__device__ float g_sum_u[(size_t)NU_MAX * DD];
__device__ float g_sum_i[(size_t)NI_MAX * DD];
__device__ float g_h1u[(size_t)NU_MAX * DD];
__device__ float g_h1i[(size_t)NI_MAX * DD];
__device__ __align__(16) __half g_xh_u[(size_t)NU_MAX * DD];   // fp16 copy of x_user
__device__ __align__(16) __half g_xh_i[(size_t)NI_MAX * DD];   // fp16 copy of x_item
__device__ __align__(16) __half g_h1h_u[(size_t)NU_MAX * DD];  // fp16 copy of h1u
__device__ __align__(16) __half g_h1h_i[(size_t)NI_MAX * DD];  // fp16 copy of h1i
__device__ int g_deg_u[NU_MAX];
__device__ int g_deg_i[NI_MAX];
__device__ int g_off_u[NU_MAX + 1];
__device__ int g_off_i[NI_MAX + 1];
__device__ int g_cur_u[NU_MAX];
__device__ int g_cur_i[NI_MAX];
__device__ int g_adj_u[E_MAX];
__device__ int g_adj_i[E_MAX];
__device__ int g_bsum[256];
// fp16 weights, 4 cfgs. Per cfg: [32 kb][128 n][8 k] fp16 = 32768 fp16.
__device__ __align__(16) __half g_wtb[4 * 32768];

// ---------------- weight prep: combine + fp16 + block layout ----------------
__global__ void prep_weights(__half* __restrict__ dst,
                             const float* __restrict__ Wr,
                             const float* __restrict__ LW,
                             const float* __restrict__ Wl) {
    int kb = blockIdx.x;
    int t = threadIdx.x;
#pragma unroll
    for (int i = 0; i < 4; ++i) {
        int e = i * 256 + t;
        int n = e >> 3, kd = e & 7;
        int k = kb * 8 + kd;
        float v;
        if (k < 128) v = Wr[n * 128 + k] + LW[n * 128 + k];
        else         v = Wl[n * 128 + (k - 128)];
        dst[kb * 1024 + e] = __float2half_rn(v);
    }
}

// ---------------- fp32 -> fp16 table conversion (both tables, one launch) ---
__global__ void conv_fp16_2(const float* __restrict__ A, __half* __restrict__ HA, int nA,
                            const float* __restrict__ B, __half* __restrict__ HB, int nB) {
    int i = (blockIdx.x * blockDim.x + threadIdx.x) * 8;
    const float* src; __half* dst;
    if (i < nA) { src = A + i; dst = HA + i; }
    else {
        i -= nA;
        if (i >= nB) return;
        src = B + i; dst = HB + i;
    }
    float4 v0 = *(const float4*)(src);
    float4 v1 = *(const float4*)(src + 4);
    __half2 h0 = __floats2half2_rn(v0.x, v0.y);
    __half2 h1 = __floats2half2_rn(v0.z, v0.w);
    __half2 h2 = __floats2half2_rn(v1.x, v1.y);
    __half2 h3 = __floats2half2_rn(v1.z, v1.w);
    uint4 o = make_uint4(*(uint32_t*)&h0, *(uint32_t*)&h1,
                         *(uint32_t*)&h2, *(uint32_t*)&h3);
    *(uint4*)(dst) = o;
}

// ---------------- CSR build ----------------
__global__ void count_deg(const int* __restrict__ iu_dst, const int* __restrict__ ui_dst,
                          int E, int* __restrict__ degU, int* __restrict__ degI) {
    int i = blockIdx.x * blockDim.x + threadIdx.x;
    if (i < E) atomicAdd(&degU[iu_dst[i]], 1);
    else { i -= E; if (i < E) atomicAdd(&degI[ui_dst[i]], 1); }
}

__global__ void scan_part(const int* __restrict__ degU, int nU,
                          const int* __restrict__ degI, int nI,
                          int* __restrict__ offU, int* __restrict__ offI,
                          int* __restrict__ bsum, int nbU) {
    __shared__ int warp_s[32];
    int b = blockIdx.x;
    const int* deg; int* off; int n; int idx0;
    if (b < nbU) { deg = degU; off = offU; n = nU; idx0 = b * SCAN_B; }
    else         { deg = degI; off = offI; n = nI; idx0 = (b - nbU) * SCAN_B; }
    int i = idx0 + threadIdx.x;
    int v = (i < n) ? deg[i] : 0;
    int lane = threadIdx.x & 31, wrp = threadIdx.x >> 5;
    int inc = v;
#pragma unroll
    for (int o = 1; o < 32; o <<= 1) {
        int t = __shfl_up_sync(0xffffffffu, inc, o);
        if (lane >= o) inc += t;
    }
    if (lane == 31) warp_s[wrp] = inc;
    __syncthreads();
    if (wrp == 0) {
        int wv = warp_s[lane];
#pragma unroll
        for (int o = 1; o < 32; o <<= 1) {
            int t = __shfl_up_sync(0xffffffffu, wv, o);
            if (lane >= o) wv += t;
        }
        warp_s[lane] = wv;
    }
    __syncthreads();
    int base = (wrp > 0) ? warp_s[wrp - 1] : 0;
    int excl = base + inc - v;
    if (i < n) off[i] = excl;
    if (threadIdx.x == SCAN_B - 1) bsum[b] = base + inc;
}

__global__ void scan_top(int* __restrict__ bsum, int nbU, int nbI,
                         int* __restrict__ offU, int nU,
                         int* __restrict__ offI, int nI) {
    if (threadIdx.x == 0) {
        int acc = 0;
        for (int i = 0; i < nbU; ++i) { int t = bsum[i]; bsum[i] = acc; acc += t; }
        offU[nU] = acc;
    }
    if (threadIdx.x == 1) {
        int acc = 0;
        for (int i = nbU; i < nbU + nbI; ++i) { int t = bsum[i]; bsum[i] = acc; acc += t; }
        offI[nI] = acc;
    }
}

__global__ void scan_add(int* __restrict__ offU, int* __restrict__ curU, int nU,
                         int* __restrict__ offI, int* __restrict__ curI, int nI,
                         const int* __restrict__ bsum, int nbU) {
    int i = blockIdx.x * blockDim.x + threadIdx.x;
    if (i < nU) {
        int v = offU[i] + bsum[i / SCAN_B];
        offU[i] = v; curU[i] = v;
    } else {
        i -= nU;
        if (i < nI) {
            int v = offI[i] + bsum[nbU + i / SCAN_B];
            offI[i] = v; curI[i] = v;
        }
    }
}

__global__ void fill_adj(const int* __restrict__ iu_src, const int* __restrict__ iu_dst,
                         const int* __restrict__ ui_src, const int* __restrict__ ui_dst,
                         int E, int* __restrict__ curU, int* __restrict__ adjU,
                         int* __restrict__ curI, int* __restrict__ adjI) {
    int i = blockIdx.x * blockDim.x + threadIdx.x;
    if (i < E) {
        int p = atomicAdd(&curU[iu_dst[i]], 1);
        adjU[p] = iu_src[i];
    } else {
        i -= E;
        if (i < E) {
            int p = atomicAdd(&curI[ui_dst[i]], 1);
            adjI[p] = ui_src[i];
        }
    }
}

// ---------------- gather aggregation (fp16 feats; one warp/dst; MLP=4) ------
__global__ void gather_agg2(const __half* __restrict__ srcU, const int* __restrict__ adjU,
                            const int* __restrict__ offU, float* __restrict__ outU, int nU,
                            const __half* __restrict__ srcI, const int* __restrict__ adjI,
                            const int* __restrict__ offI, float* __restrict__ outI, int nI) {
    int w = (blockIdx.x * blockDim.x + threadIdx.x) >> 5;
    int lane = threadIdx.x & 31;
    const __half* feat; const int* adj; const int* off; float* out; int d;
    if (w < nU) { feat = srcU; adj = adjU; off = offU; out = outU; d = w; }
    else {
        w -= nU;
        if (w >= nI) return;
        feat = srcI; adj = adjI; off = offI; out = outI; d = w;
    }
    int beg = __ldg(off + d), end = __ldg(off + d + 1);
    float4 a0 = make_float4(0.f, 0.f, 0.f, 0.f);
    float4 a1 = make_float4(0.f, 0.f, 0.f, 0.f);
    int base = beg;
    auto addrow = [&](int s, float4& acc) {
        uint2 u = *(const uint2*)(feat + (size_t)s * DD + lane * 4);
        float2 f0 = __half22float2(*(__half2*)&u.x);
        float2 f1 = __half22float2(*(__half2*)&u.y);
        acc.x += f0.x; acc.y += f0.y; acc.z += f1.x; acc.w += f1.y;
    };
    for (; base + 4 <= end; base += 4) {
        int s0 = __ldg(adj + base + 0);
        int s1 = __ldg(adj + base + 1);
        int s2 = __ldg(adj + base + 2);
        int s3 = __ldg(adj + base + 3);
        addrow(s0, a0); addrow(s1, a1); addrow(s2, a0); addrow(s3, a1);
    }
    for (; base < end; ++base) addrow(__ldg(adj + base), a0);
    a0.x += a1.x; a0.y += a1.y; a0.z += a1.z; a0.w += a1.w;
    *(float4*)(out + (size_t)d * DD + lane * 4) = a0;
}

// ---------------- tensor-core fused SAGE GEMM (fp16 2-term; merged pair) ----
// out[m,:] = act( X[m,:] @ Wc^T + (1/max(deg,1)) * S[m,:] @ Wl^T + b1 + b2 )
__device__ __forceinline__ void ldsm4(uint32_t* r, const void* p) {
    uint32_t a = (uint32_t)__cvta_generic_to_shared(p);
    asm volatile("ldmatrix.sync.aligned.m8n8.x4.shared.b16 {%0,%1,%2,%3}, [%4];\n"
                 : "=r"(r[0]), "=r"(r[1]), "=r"(r[2]), "=r"(r[3]) : "r"(a));
}
__device__ __forceinline__ void mma16816(float* c, const uint32_t* a, const uint32_t* b) {
    asm volatile("mma.sync.aligned.m16n8k16.row.col.f32.f16.f16.f32 "
                 "{%0,%1,%2,%3}, {%4,%5,%6,%7}, {%8,%9}, {%0,%1,%2,%3};\n"
                 : "+f"(c[0]), "+f"(c[1]), "+f"(c[2]), "+f"(c[3])
                 : "r"(a[0]), "r"(a[1]), "r"(a[2]), "r"(a[3]), "r"(b[0]), "r"(b[1]));
}
__device__ __forceinline__ void cp_async16(void* smem_dst, const void* gsrc) {
    uint32_t a = (uint32_t)__cvta_generic_to_shared(smem_dst);
    asm volatile("cp.async.cg.shared.global [%0], [%1], 16;\n"
                 :: "r"(a), "l"(gsrc) : "memory");
}
#define CP_ASYNC_COMMIT() asm volatile("cp.async.commit_group;\n" ::: "memory")
#define CP_ASYNC_WAIT0()  asm volatile("cp.async.wait_group 0;\n" ::: "memory")

#define SM_BYTES 50176

__global__ __launch_bounds__(512, 1)
void sage_gemm2(const float* __restrict__ X0, const float* __restrict__ S0,
                const int* __restrict__ deg0, const __half* __restrict__ Wt0,
                const float* __restrict__ b1_0, const float* __restrict__ b2_0,
                float* __restrict__ out0, __half* __restrict__ outh0, int n0, int split,
                const float* __restrict__ X1, const float* __restrict__ S1,
                const int* __restrict__ deg1, const __half* __restrict__ Wt1,
                const float* __restrict__ b1_1, const float* __restrict__ b2_1,
                float* __restrict__ out1, __half* __restrict__ outh1, int n1,
                int do_relu) {
    extern __shared__ char sm_raw[];
    __half* Wsm = (__half*)sm_raw;                    // 2 stages x 4096
    __half* Asm = (__half*)(sm_raw + 16384);          // 2 stages x 8192 (hi+lo)
    float* scs = (float*)(sm_raw + 49152);
    float* bss = (float*)(sm_raw + 49664);

    const float* X; const float* S; const int* deg; const __half* Wt;
    const float* b1; const float* b2; float* out; __half* outh; int nrows, bidx;
    if ((int)blockIdx.x < split) {
        X = X0; S = S0; deg = deg0; Wt = Wt0; b1 = b1_0; b2 = b2_0;
        out = out0; outh = outh0; nrows = n0; bidx = blockIdx.x;
    } else {
        X = X1; S = S1; deg = deg1; Wt = Wt1; b1 = b1_1; b2 = b2_1;
        out = out1; outh = outh1; nrows = n1; bidx = blockIdx.x - split;
    }

    const int tid = threadIdx.x;
    const int lane = tid & 31;
    const int wid = tid >> 5;
    const int m0w = (wid & 3) * 32;
    const int n0w = (wid >> 2) * 32;
    const int m0 = bidx * 128;

    const int sel = lane >> 3, lr = lane & 7;
    const int a_ro = ((sel & 1) << 3) + lr;
    const int a_kb = sel >> 1;
    const int b_ro = ((sel >> 1) << 3) + lr;
    const int b_kb = sel & 1;

    const int arow = tid >> 2;
    const int aq = tid & 3;

    if (tid < 128) {
        int c = (m0 + tid < nrows) ? deg[m0 + tid] : 1;
        scs[tid] = 1.0f / fmaxf((float)c, 1.0f);
        bss[tid] = b1[tid] + b2[tid];
    }

    float acc[2][4][4];
#pragma unroll
    for (int i = 0; i < 2; ++i)
#pragma unroll
        for (int j = 0; j < 4; ++j)
#pragma unroll
            for (int q = 0; q < 4; ++q) acc[i][j][q] = 0.f;

    float4 pfA[2];

    auto loadW = [&](int c, int st) {
        const char* sh = (const char*)(Wt + c * 4096) + tid * 16;
        char* dh = (char*)(Wsm + st * 4096) + tid * 16;
        cp_async16(dh, sh);
        CP_ASYNC_COMMIT();
    };
    auto loadA = [&](int c) {
        const float* src = (c < 4) ? X : S;
        int kc = (c & 3) * 32 + aq * 8;
        if (m0 + arow < nrows) {
            const float* row = src + (size_t)(m0 + arow) * DD + kc;
            pfA[0] = *(const float4*)(row);
            pfA[1] = *(const float4*)(row + 4);
        } else {
            pfA[0] = make_float4(0.f, 0.f, 0.f, 0.f);
            pfA[1] = make_float4(0.f, 0.f, 0.f, 0.f);
        }
    };
    auto storeA = [&](int c, int st) {
        float s = (c >= 4) ? scs[arow] : 1.0f;
        __half* ab = Asm + st * 8192;
        int idx = (aq * 128 + arow) * 8;
        uint32_t hv[4], lv[4];
#pragma unroll
        for (int h = 0; h < 2; ++h) {
            float4 v = pfA[h];
            v.x *= s; v.y *= s; v.z *= s; v.w *= s;
            __half2 h0 = __floats2half2_rn(v.x, v.y);
            __half2 h1 = __floats2half2_rn(v.z, v.w);
            hv[h * 2 + 0] = *(uint32_t*)&h0;
            hv[h * 2 + 1] = *(uint32_t*)&h1;
            __half2 l0 = __floats2half2_rn(v.x - __half2float(h0.x),
                                           v.y - __half2float(h0.y));
            __half2 l1 = __floats2half2_rn(v.z - __half2float(h1.x),
                                           v.w - __half2float(h1.y));
            lv[h * 2 + 0] = *(uint32_t*)&l0;
            lv[h * 2 + 1] = *(uint32_t*)&l1;
        }
        *(uint4*)(ab + idx) = make_uint4(hv[0], hv[1], hv[2], hv[3]);
        *(uint4*)(ab + 4096 + idx) = make_uint4(lv[0], lv[1], lv[2], lv[3]);
    };

    loadW(0, 0);
    loadA(0);
    storeA(0, 0);
    CP_ASYNC_WAIT0();
    __syncthreads();

    for (int c = 0; c < 8; ++c) {
        int st = c & 1;
        if (c < 7) { loadW(c + 1, 1 - st); loadA(c + 1); }
#pragma unroll
        for (int kk = 0; kk < 2; ++kk) {
            uint32_t ah[2][4], al[2][4], bh[2][4];
#pragma unroll
            for (int mt = 0; mt < 2; ++mt) {
                const __half* p = Asm + st * 8192 +
                    (((2 * kk + a_kb) * 128) + m0w + mt * 16 + a_ro) * 8;
                ldsm4(ah[mt], p);
                ldsm4(al[mt], p + 4096);
            }
#pragma unroll
            for (int ng = 0; ng < 2; ++ng) {
                const __half* p = Wsm + st * 4096 +
                    (((2 * kk + b_kb) * 128) + n0w + ng * 16 + b_ro) * 8;
                ldsm4(bh[ng], p);
            }
#pragma unroll
            for (int mt = 0; mt < 2; ++mt)
#pragma unroll
                for (int nt = 0; nt < 4; ++nt) {
                    const uint32_t* pbh = &bh[nt >> 1][(nt & 1) * 2];
                    mma16816(acc[mt][nt], ah[mt], pbh);
                    mma16816(acc[mt][nt], al[mt], pbh);
                }
        }
        if (c < 7) {
            storeA(c + 1, 1 - st);
            CP_ASYNC_WAIT0();
            __syncthreads();
        }
    }

    // epilogue: bias (+relu), fp32 stores (+fp16 mirror for layer-1)
#pragma unroll
    for (int mt = 0; mt < 2; ++mt) {
        int rbase = m0w + mt * 16 + (lane >> 2);
#pragma unroll
        for (int half = 0; half < 2; ++half) {
            int r = rbase + half * 8;
            if (m0 + r >= nrows) continue;
            float* orow = out + (size_t)(m0 + r) * DD;
            __half* ohrow = do_relu ? (outh + (size_t)(m0 + r) * DD) : (__half*)0;
#pragma unroll
            for (int nt = 0; nt < 4; ++nt) {
                int col = n0w + nt * 8 + (lane & 3) * 2;
                float v0 = acc[mt][nt][half * 2 + 0] + bss[col];
                float v1 = acc[mt][nt][half * 2 + 1] + bss[col + 1];
                if (do_relu) { v0 = fmaxf(v0, 0.f); v1 = fmaxf(v1, 0.f); }
                *(float2*)(orow + col) = make_float2(v0, v1);
                if (ohrow) {
                    __half2 hv = __floats2half2_rn(v0, v1);
                    *(__half2*)(ohrow + col) = hv;
                }
            }
        }
    }
}

// ---------------- host orchestration ----------------
extern "C" void kernel_launch(void* const* d_in, const int* in_sizes, int n_in,
                              void* d_out, int out_size) {
    const float* x_user = (const float*)d_in[0];
    const float* x_item = (const float*)d_in[1];
    const int* ui_src = (const int*)d_in[2];
    const int* ui_dst = (const int*)d_in[3];
    const int* iu_src = (const int*)d_in[4];
    const int* iu_dst = (const int*)d_in[5];
    const float* W1l_ui = (const float*)d_in[6];
    const float* b1_ui  = (const float*)d_in[7];
    const float* W1r_ui = (const float*)d_in[8];
    const float* W1l_iu = (const float*)d_in[9];
    const float* b1_iu  = (const float*)d_in[10];
    const float* W1r_iu = (const float*)d_in[11];
    const float* L1W_u  = (const float*)d_in[12];
    const float* L1b_u  = (const float*)d_in[13];
    const float* L1W_i  = (const float*)d_in[14];
    const float* L1b_i  = (const float*)d_in[15];
    const float* W2l_ui = (const float*)d_in[16];
    const float* b2_ui  = (const float*)d_in[17];
    const float* W2r_ui = (const float*)d_in[18];
    const float* W2l_iu = (const float*)d_in[19];
    const float* b2_iu  = (const float*)d_in[20];
    const float* W2r_iu = (const float*)d_in[21];
    const float* L2W_u  = (const float*)d_in[22];
    const float* L2b_u  = (const float*)d_in[23];
    const float* L2W_i  = (const float*)d_in[24];
    const float* L2b_i  = (const float*)d_in[25];

    const int NU = in_sizes[0] / DD;
    const int NI = in_sizes[1] / DD;
    const int E = in_sizes[2];

    float *sum_u, *sum_i, *h1u, *h1i;
    __half *xh_u, *xh_i, *h1h_u, *h1h_i, *wtb;
    int *deg_u, *deg_i, *off_u, *off_i, *cur_u, *cur_i, *adj_u, *adj_i, *bsum;
    cudaGetSymbolAddress((void**)&sum_u, g_sum_u);
    cudaGetSymbolAddress((void**)&sum_i, g_sum_i);
    cudaGetSymbolAddress((void**)&h1u, g_h1u);
    cudaGetSymbolAddress((void**)&h1i, g_h1i);
    cudaGetSymbolAddress((void**)&xh_u, g_xh_u);
    cudaGetSymbolAddress((void**)&xh_i, g_xh_i);
    cudaGetSymbolAddress((void**)&h1h_u, g_h1h_u);
    cudaGetSymbolAddress((void**)&h1h_i, g_h1h_i);
    cudaGetSymbolAddress((void**)&deg_u, g_deg_u);
    cudaGetSymbolAddress((void**)&deg_i, g_deg_i);
    cudaGetSymbolAddress((void**)&off_u, g_off_u);
    cudaGetSymbolAddress((void**)&off_i, g_off_i);
    cudaGetSymbolAddress((void**)&cur_u, g_cur_u);
    cudaGetSymbolAddress((void**)&cur_i, g_cur_i);
    cudaGetSymbolAddress((void**)&adj_u, g_adj_u);
    cudaGetSymbolAddress((void**)&adj_i, g_adj_i);
    cudaGetSymbolAddress((void**)&bsum, g_bsum);
    cudaGetSymbolAddress((void**)&wtb, g_wtb);

    cudaFuncSetAttribute(sage_gemm2, cudaFuncAttributeMaxDynamicSharedMemorySize,
                         SM_BYTES);

    float* out_u = (float*)d_out;
    float* out_i = out_u + (size_t)NU * DD;

    // weight prep (fp16 block layout)
    prep_weights<<<32, 256>>>(wtb + 0 * 32768, W1r_iu, L1W_u, W1l_iu);
    prep_weights<<<32, 256>>>(wtb + 1 * 32768, W1r_ui, L1W_i, W1l_ui);
    prep_weights<<<32, 256>>>(wtb + 2 * 32768, W2r_iu, L2W_u, W2l_iu);
    prep_weights<<<32, 256>>>(wtb + 3 * 32768, W2r_ui, L2W_i, W2l_ui);

    // fp16 copies of input features (for gather)
    {
        int nA = NU * DD, nB = NI * DD;
        int thr = (nA + nB) / 8;
        conv_fp16_2<<<(thr + 255) / 256, 256>>>(x_user, xh_u, nA, x_item, xh_i, nB);
    }

    // CSR build (once; shared by both layers)
    cudaMemsetAsync(deg_u, 0, NU * sizeof(int));
    cudaMemsetAsync(deg_i, 0, NI * sizeof(int));
    count_deg<<<(2 * E + 255) / 256, 256>>>(iu_dst, ui_dst, E, deg_u, deg_i);
    int nbU = (NU + SCAN_B - 1) / SCAN_B, nbI = (NI + SCAN_B - 1) / SCAN_B;
    scan_part<<<nbU + nbI, SCAN_B>>>(deg_u, NU, deg_i, NI, off_u, off_i, bsum, nbU);
    scan_top<<<1, 32>>>(bsum, nbU, nbI, off_u, NU, off_i, NI);
    scan_add<<<(NU + NI + 255) / 256, 256>>>(off_u, cur_u, NU, off_i, cur_i, NI, bsum, nbU);
    fill_adj<<<(2 * E + 255) / 256, 256>>>(iu_src, iu_dst, ui_src, ui_dst, E,
                                           cur_u, adj_u, cur_i, adj_i);

    int gblocks = ((NU + NI) * 32 + 255) / 256;
    // layer 1 aggregation (fp16 reads)
    gather_agg2<<<gblocks, 256>>>(xh_i, adj_u, off_u, sum_u, NU,
                                  xh_u, adj_i, off_i, sum_i, NI);

    int gu = (NU + 127) / 128, gi = (NI + 127) / 128;
    // layer 1 GEMMs (merged; writes h1 fp32 + fp16 mirror)
    sage_gemm2<<<gu + gi, 512, SM_BYTES>>>(
        x_user, sum_u, deg_u, wtb + 0 * 32768, b1_iu, L1b_u, h1u, h1h_u, NU, gu,
        x_item, sum_i, deg_i, wtb + 1 * 32768, b1_ui, L1b_i, h1i, h1h_i, NI, 1);

    // layer 2 aggregation (fp16 reads of h1 mirrors)
    gather_agg2<<<gblocks, 256>>>(h1h_i, adj_u, off_u, sum_u, NU,
                                  h1h_u, adj_i, off_i, sum_i, NI);

    // layer 2 GEMMs (merged; fp32 output only)
    sage_gemm2<<<gu + gi, 512, SM_BYTES>>>(
        h1u, sum_u, deg_u, wtb + 2 * 32768, b2_iu, L2b_u, out_u, (__half*)0, NU, gu,
        h1i, sum_i, deg_i, wtb + 3 * 32768, b2_ui, L2b_i, out_i, (__half*)0, NI, 0);
}

// round 12
// speedup vs baseline: 1.2063x; 1.2063x over previous
#include <cuda_runtime.h>
#include <cuda_fp16.h>
#include <cstdint>
#include <cstddef>

// Problem constants (fixed by the dataset)
#define NU_MAX 100000
#define NI_MAX 50000
#define E_MAX 300000
#define DD 128
#define PAD_ROWS 128
#define SCAN_B 1024

// ---------------- device scratch (no allocations allowed) ----------------
// fp16 feature tables (padded so OOB tile rows stay in-bounds)
__device__ __align__(16) __half g_xh_u[(size_t)(NU_MAX + PAD_ROWS) * DD];
__device__ __align__(16) __half g_xh_i[(size_t)(NI_MAX + PAD_ROWS) * DD];
__device__ __align__(16) __half g_h1h_u[(size_t)(NU_MAX + PAD_ROWS) * DD];
__device__ __align__(16) __half g_h1h_i[(size_t)(NI_MAX + PAD_ROWS) * DD];
__device__ __align__(16) __half g_mh_u[(size_t)(NU_MAX + PAD_ROWS) * DD];  // fp16 mean
__device__ __align__(16) __half g_mh_i[(size_t)(NI_MAX + PAD_ROWS) * DD];
__device__ int g_deg_u[NU_MAX];
__device__ int g_deg_i[NI_MAX];
__device__ int g_off_u[NU_MAX + 1];
__device__ int g_off_i[NI_MAX + 1];
__device__ int g_cur_u[NU_MAX];
__device__ int g_cur_i[NI_MAX];
__device__ int g_adj_u[E_MAX];
__device__ int g_adj_i[E_MAX];
__device__ int g_bsum[256];
// fp16 weights, 4 cfgs. Per cfg: [32 kb][128 n][8 k] fp16 = 32768 fp16.
__device__ __align__(16) __half g_wtb[4 * 32768];

// ---------------- weight prep: all 4 cfgs in one launch ----------------
__global__ void prep_weights4(const float* __restrict__ Wr0, const float* __restrict__ LW0,
                              const float* __restrict__ Wl0,
                              const float* __restrict__ Wr1, const float* __restrict__ LW1,
                              const float* __restrict__ Wl1,
                              const float* __restrict__ Wr2, const float* __restrict__ LW2,
                              const float* __restrict__ Wl2,
                              const float* __restrict__ Wr3, const float* __restrict__ LW3,
                              const float* __restrict__ Wl3,
                              __half* __restrict__ dst_base) {
    int cfg = blockIdx.x >> 5;
    int kb = blockIdx.x & 31;
    const float* Wr; const float* LW; const float* Wl;
    if (cfg == 0)      { Wr = Wr0; LW = LW0; Wl = Wl0; }
    else if (cfg == 1) { Wr = Wr1; LW = LW1; Wl = Wl1; }
    else if (cfg == 2) { Wr = Wr2; LW = LW2; Wl = Wl2; }
    else               { Wr = Wr3; LW = LW3; Wl = Wl3; }
    __half* dst = dst_base + cfg * 32768;
    int t = threadIdx.x;
#pragma unroll
    for (int i = 0; i < 4; ++i) {
        int e = i * 256 + t;
        int n = e >> 3, kd = e & 7;
        int k = kb * 8 + kd;
        float v;
        if (k < 128) v = Wr[n * 128 + k] + LW[n * 128 + k];
        else         v = Wl[n * 128 + (k - 128)];
        dst[kb * 1024 + e] = __float2half_rn(v);
    }
}

// ---------------- fp32 -> fp16 table conversion (both tables, one launch) ---
__global__ void conv_fp16_2(const float* __restrict__ A, __half* __restrict__ HA, int nA,
                            const float* __restrict__ B, __half* __restrict__ HB, int nB) {
    int i = (blockIdx.x * blockDim.x + threadIdx.x) * 8;
    const float* src; __half* dst;
    if (i < nA) { src = A + i; dst = HA + i; }
    else {
        i -= nA;
        if (i >= nB) return;
        src = B + i; dst = HB + i;
    }
    float4 v0 = *(const float4*)(src);
    float4 v1 = *(const float4*)(src + 4);
    __half2 h0 = __floats2half2_rn(v0.x, v0.y);
    __half2 h1 = __floats2half2_rn(v0.z, v0.w);
    __half2 h2 = __floats2half2_rn(v1.x, v1.y);
    __half2 h3 = __floats2half2_rn(v1.z, v1.w);
    uint4 o = make_uint4(*(uint32_t*)&h0, *(uint32_t*)&h1,
                         *(uint32_t*)&h2, *(uint32_t*)&h3);
    *(uint4*)(dst) = o;
}

// ---------------- CSR build ----------------
__global__ void count_deg(const int* __restrict__ iu_dst, const int* __restrict__ ui_dst,
                          int E, int* __restrict__ degU, int* __restrict__ degI) {
    int i = blockIdx.x * blockDim.x + threadIdx.x;
    if (i < E) atomicAdd(&degU[iu_dst[i]], 1);
    else { i -= E; if (i < E) atomicAdd(&degI[ui_dst[i]], 1); }
}

__global__ void scan_part(const int* __restrict__ degU, int nU,
                          const int* __restrict__ degI, int nI,
                          int* __restrict__ offU, int* __restrict__ offI,
                          int* __restrict__ bsum, int nbU) {
    __shared__ int warp_s[32];
    int b = blockIdx.x;
    const int* deg; int* off; int n; int idx0;
    if (b < nbU) { deg = degU; off = offU; n = nU; idx0 = b * SCAN_B; }
    else         { deg = degI; off = offI; n = nI; idx0 = (b - nbU) * SCAN_B; }
    int i = idx0 + threadIdx.x;
    int v = (i < n) ? deg[i] : 0;
    int lane = threadIdx.x & 31, wrp = threadIdx.x >> 5;
    int inc = v;
#pragma unroll
    for (int o = 1; o < 32; o <<= 1) {
        int t = __shfl_up_sync(0xffffffffu, inc, o);
        if (lane >= o) inc += t;
    }
    if (lane == 31) warp_s[wrp] = inc;
    __syncthreads();
    if (wrp == 0) {
        int wv = warp_s[lane];
#pragma unroll
        for (int o = 1; o < 32; o <<= 1) {
            int t = __shfl_up_sync(0xffffffffu, wv, o);
            if (lane >= o) wv += t;
        }
        warp_s[lane] = wv;
    }
    __syncthreads();
    int base = (wrp > 0) ? warp_s[wrp - 1] : 0;
    int excl = base + inc - v;
    if (i < n) off[i] = excl;
    if (threadIdx.x == SCAN_B - 1) bsum[b] = base + inc;
}

// smem-staged top-level scan (147 elems; avoids serial L2 round-trips)
__global__ void scan_top(int* __restrict__ bsum, int nbU, int nbI,
                         int* __restrict__ offU, int nU,
                         int* __restrict__ offI, int nI) {
    __shared__ int s[256];
    int t = threadIdx.x;
    int ntot = nbU + nbI;
    if (t < ntot) s[t] = bsum[t];
    __syncthreads();
    if (t == 0) {
        int acc = 0;
        for (int i = 0; i < nbU; ++i) { int tmp = s[i]; s[i] = acc; acc += tmp; }
        offU[nU] = acc;
    }
    if (t == 1) {
        int acc = 0;
        for (int i = nbU; i < ntot; ++i) { int tmp = s[i]; s[i] = acc; acc += tmp; }
        offI[nI] = acc;
    }
    __syncthreads();
    if (t < ntot) bsum[t] = s[t];
}

__global__ void scan_add(int* __restrict__ offU, int* __restrict__ curU, int nU,
                         int* __restrict__ offI, int* __restrict__ curI, int nI,
                         const int* __restrict__ bsum, int nbU) {
    int i = blockIdx.x * blockDim.x + threadIdx.x;
    if (i < nU) {
        int v = offU[i] + bsum[i / SCAN_B];
        offU[i] = v; curU[i] = v;
    } else {
        i -= nU;
        if (i < nI) {
            int v = offI[i] + bsum[nbU + i / SCAN_B];
            offI[i] = v; curI[i] = v;
        }
    }
}

__global__ void fill_adj(const int* __restrict__ iu_src, const int* __restrict__ iu_dst,
                         const int* __restrict__ ui_src, const int* __restrict__ ui_dst,
                         int E, int* __restrict__ curU, int* __restrict__ adjU,
                         int* __restrict__ curI, int* __restrict__ adjI) {
    int i = blockIdx.x * blockDim.x + threadIdx.x;
    if (i < E) {
        int p = atomicAdd(&curU[iu_dst[i]], 1);
        adjU[p] = iu_src[i];
    } else {
        i -= E;
        if (i < E) {
            int p = atomicAdd(&curI[ui_dst[i]], 1);
            adjI[p] = ui_src[i];
        }
    }
}

// ---------------- gather MEAN (fp16 in, fp16 out; one warp/dst; MLP=4) ------
__global__ void gather_mean2(const __half* __restrict__ srcU, const int* __restrict__ adjU,
                             const int* __restrict__ offU, __half* __restrict__ outU, int nU,
                             const __half* __restrict__ srcI, const int* __restrict__ adjI,
                             const int* __restrict__ offI, __half* __restrict__ outI, int nI) {
    int w = (blockIdx.x * blockDim.x + threadIdx.x) >> 5;
    int lane = threadIdx.x & 31;
    const __half* feat; const int* adj; const int* off; __half* out; int d;
    if (w < nU) { feat = srcU; adj = adjU; off = offU; out = outU; d = w; }
    else {
        w -= nU;
        if (w >= nI) return;
        feat = srcI; adj = adjI; off = offI; out = outI; d = w;
    }
    int beg = __ldg(off + d), end = __ldg(off + d + 1);
    float4 a0 = make_float4(0.f, 0.f, 0.f, 0.f);
    float4 a1 = make_float4(0.f, 0.f, 0.f, 0.f);
    int base = beg;
    auto addrow = [&](int s, float4& acc) {
        uint2 u = *(const uint2*)(feat + (size_t)s * DD + lane * 4);
        float2 f0 = __half22float2(*(__half2*)&u.x);
        float2 f1 = __half22float2(*(__half2*)&u.y);
        acc.x += f0.x; acc.y += f0.y; acc.z += f1.x; acc.w += f1.y;
    };
    for (; base + 4 <= end; base += 4) {
        int s0 = __ldg(adj + base + 0);
        int s1 = __ldg(adj + base + 1);
        int s2 = __ldg(adj + base + 2);
        int s3 = __ldg(adj + base + 3);
        addrow(s0, a0); addrow(s1, a1); addrow(s2, a0); addrow(s3, a1);
    }
    for (; base < end; ++base) addrow(__ldg(adj + base), a0);
    float inv = 1.0f / (float)max(end - beg, 1);
    a0.x = (a0.x + a1.x) * inv; a0.y = (a0.y + a1.y) * inv;
    a0.z = (a0.z + a1.z) * inv; a0.w = (a0.w + a1.w) * inv;
    __half2 o0 = __floats2half2_rn(a0.x, a0.y);
    __half2 o1 = __floats2half2_rn(a0.z, a0.w);
    *(uint2*)(out + (size_t)d * DD + lane * 4) =
        make_uint2(*(uint32_t*)&o0, *(uint32_t*)&o1);
}

// ---------------- pure-fp16 fused SAGE GEMM (merged pair) ----------------
// out[m,:] = act( X[m,:] @ Wc^T + mean[m,:] @ Wl^T + b1 + b2 )
__device__ __forceinline__ void ldsm4(uint32_t* r, const void* p) {
    uint32_t a = (uint32_t)__cvta_generic_to_shared(p);
    asm volatile("ldmatrix.sync.aligned.m8n8.x4.shared.b16 {%0,%1,%2,%3}, [%4];\n"
                 : "=r"(r[0]), "=r"(r[1]), "=r"(r[2]), "=r"(r[3]) : "r"(a));
}
__device__ __forceinline__ void mma16816(float* c, const uint32_t* a, const uint32_t* b) {
    asm volatile("mma.sync.aligned.m16n8k16.row.col.f32.f16.f16.f32 "
                 "{%0,%1,%2,%3}, {%4,%5,%6,%7}, {%8,%9}, {%0,%1,%2,%3};\n"
                 : "+f"(c[0]), "+f"(c[1]), "+f"(c[2]), "+f"(c[3])
                 : "r"(a[0]), "r"(a[1]), "r"(a[2]), "r"(a[3]), "r"(b[0]), "r"(b[1]));
}
__device__ __forceinline__ void cp_async16(void* smem_dst, const void* gsrc) {
    uint32_t a = (uint32_t)__cvta_generic_to_shared(smem_dst);
    asm volatile("cp.async.cg.shared.global [%0], [%1], 16;\n"
                 :: "r"(a), "l"(gsrc) : "memory");
}
#define CP_ASYNC_COMMIT() asm volatile("cp.async.commit_group;\n" ::: "memory")
#define CP_ASYNC_WAIT0()  asm volatile("cp.async.wait_group 0;\n" ::: "memory")

// smem: W 2 stages x 8192 B = 16384; A 2 stages x 8192 B = 16384 (at 16384)
//       bss 128 f32 (at 32768)
#define SM_BYTES 33792

__global__ __launch_bounds__(512, 1)
void sage_gemm2(const __half* __restrict__ Xh0, const __half* __restrict__ Mh0,
                const __half* __restrict__ Wt0,
                const float* __restrict__ b1_0, const float* __restrict__ b2_0,
                float* __restrict__ out0, __half* __restrict__ outh0, int n0, int split,
                const __half* __restrict__ Xh1, const __half* __restrict__ Mh1,
                const __half* __restrict__ Wt1,
                const float* __restrict__ b1_1, const float* __restrict__ b2_1,
                float* __restrict__ out1, __half* __restrict__ outh1, int n1,
                int do_relu) {
    extern __shared__ char sm_raw[];
    __half* Wsm = (__half*)sm_raw;                    // 2 stages x 4096 halves
    __half* Asm = (__half*)(sm_raw + 16384);          // 2 stages x 4096 halves
    float* bss = (float*)(sm_raw + 32768);

    const __half* Xh; const __half* Mh; const __half* Wt;
    const float* b1; const float* b2; float* out; __half* outh; int nrows, bidx;
    if ((int)blockIdx.x < split) {
        Xh = Xh0; Mh = Mh0; Wt = Wt0; b1 = b1_0; b2 = b2_0;
        out = out0; outh = outh0; nrows = n0; bidx = blockIdx.x;
    } else {
        Xh = Xh1; Mh = Mh1; Wt = Wt1; b1 = b1_1; b2 = b2_1;
        out = out1; outh = outh1; nrows = n1; bidx = blockIdx.x - split;
    }

    const int tid = threadIdx.x;
    const int lane = tid & 31;
    const int wid = tid >> 5;
    const int m0w = (wid & 3) * 32;
    const int n0w = (wid >> 2) * 32;
    const int m0 = bidx * 128;

    const int sel = lane >> 3, lr = lane & 7;
    const int a_ro = ((sel & 1) << 3) + lr;
    const int a_kb = sel >> 1;
    const int b_ro = ((sel >> 1) << 3) + lr;
    const int b_kb = sel & 1;

    const int arow = tid >> 2;   // A loader: row 0..127
    const int akb = tid & 3;     // A loader: kb within chunk

    if (tid < 128) bss[tid] = b1[tid] + b2[tid];

    float acc[2][4][4];
#pragma unroll
    for (int i = 0; i < 2; ++i)
#pragma unroll
        for (int j = 0; j < 4; ++j)
#pragma unroll
            for (int q = 0; q < 4; ++q) acc[i][j][q] = 0.f;

    // W chunk c -> stage st (8 KB; 512 thr x 16 B)
    auto loadW = [&](int c, int st) {
        const char* sh = (const char*)(Wt + c * 4096) + tid * 16;
        char* dh = (char*)(Wsm + st * 4096) + tid * 16;
        cp_async16(dh, sh);
    };
    // A chunk c -> stage st, fp16 direct, block layout [kb 4][row 128][8 k]
    auto loadA = [&](int c, int st) {
        const __half* src = (c < 4) ? Xh : Mh;
        int chunk = c & 3;
        int gr = m0 + arow;
        // padded tables: rows up to nrows+127 are in-bounds
        const char* s = (const char*)(src + (size_t)gr * DD) + chunk * 64 + akb * 16;
        char* d = (char*)(Asm + st * 4096) + (akb * 128 + arow) * 16;
        cp_async16(d, s);
    };

    loadW(0, 0);
    loadA(0, 0);
    CP_ASYNC_COMMIT();
    CP_ASYNC_WAIT0();
    __syncthreads();

    for (int c = 0; c < 8; ++c) {
        int st = c & 1;
        if (c < 7) { loadW(c + 1, 1 - st); loadA(c + 1, 1 - st); CP_ASYNC_COMMIT(); }
#pragma unroll
        for (int kk = 0; kk < 2; ++kk) {
            uint32_t ah[2][4], bh[2][4];
#pragma unroll
            for (int mt = 0; mt < 2; ++mt) {
                const __half* p = Asm + st * 4096 +
                    (((2 * kk + a_kb) * 128) + m0w + mt * 16 + a_ro) * 8;
                ldsm4(ah[mt], p);
            }
#pragma unroll
            for (int ng = 0; ng < 2; ++ng) {
                const __half* p = Wsm + st * 4096 +
                    (((2 * kk + b_kb) * 128) + n0w + ng * 16 + b_ro) * 8;
                ldsm4(bh[ng], p);
            }
#pragma unroll
            for (int mt = 0; mt < 2; ++mt)
#pragma unroll
                for (int nt = 0; nt < 4; ++nt)
                    mma16816(acc[mt][nt], ah[mt], &bh[nt >> 1][(nt & 1) * 2]);
        }
        if (c < 7) {
            CP_ASYNC_WAIT0();
            __syncthreads();
        }
    }

    // epilogue: bias (+relu); layer-1 writes fp16 only, layer-2 fp32 only
#pragma unroll
    for (int mt = 0; mt < 2; ++mt) {
        int rbase = m0w + mt * 16 + (lane >> 2);
#pragma unroll
        for (int half = 0; half < 2; ++half) {
            int r = rbase + half * 8;
            if (m0 + r >= nrows) continue;
#pragma unroll
            for (int nt = 0; nt < 4; ++nt) {
                int col = n0w + nt * 8 + (lane & 3) * 2;
                float v0 = acc[mt][nt][half * 2 + 0] + bss[col];
                float v1 = acc[mt][nt][half * 2 + 1] + bss[col + 1];
                if (do_relu) {
                    v0 = fmaxf(v0, 0.f); v1 = fmaxf(v1, 0.f);
                    __half2 hv = __floats2half2_rn(v0, v1);
                    *(__half2*)(outh + (size_t)(m0 + r) * DD + col) = hv;
                } else {
                    *(float2*)(out + (size_t)(m0 + r) * DD + col) = make_float2(v0, v1);
                }
            }
        }
    }
}

// ---------------- host orchestration ----------------
extern "C" void kernel_launch(void* const* d_in, const int* in_sizes, int n_in,
                              void* d_out, int out_size) {
    const float* x_user = (const float*)d_in[0];
    const float* x_item = (const float*)d_in[1];
    const int* ui_src = (const int*)d_in[2];
    const int* ui_dst = (const int*)d_in[3];
    const int* iu_src = (const int*)d_in[4];
    const int* iu_dst = (const int*)d_in[5];
    const float* W1l_ui = (const float*)d_in[6];
    const float* b1_ui  = (const float*)d_in[7];
    const float* W1r_ui = (const float*)d_in[8];
    const float* W1l_iu = (const float*)d_in[9];
    const float* b1_iu  = (const float*)d_in[10];
    const float* W1r_iu = (const float*)d_in[11];
    const float* L1W_u  = (const float*)d_in[12];
    const float* L1b_u  = (const float*)d_in[13];
    const float* L1W_i  = (const float*)d_in[14];
    const float* L1b_i  = (const float*)d_in[15];
    const float* W2l_ui = (const float*)d_in[16];
    const float* b2_ui  = (const float*)d_in[17];
    const float* W2r_ui = (const float*)d_in[18];
    const float* W2l_iu = (const float*)d_in[19];
    const float* b2_iu  = (const float*)d_in[20];
    const float* W2r_iu = (const float*)d_in[21];
    const float* L2W_u  = (const float*)d_in[22];
    const float* L2b_u  = (const float*)d_in[23];
    const float* L2W_i  = (const float*)d_in[24];
    const float* L2b_i  = (const float*)d_in[25];

    const int NU = in_sizes[0] / DD;
    const int NI = in_sizes[1] / DD;
    const int E = in_sizes[2];

    __half *xh_u, *xh_i, *h1h_u, *h1h_i, *mh_u, *mh_i, *wtb;
    int *deg_u, *deg_i, *off_u, *off_i, *cur_u, *cur_i, *adj_u, *adj_i, *bsum;
    cudaGetSymbolAddress((void**)&xh_u, g_xh_u);
    cudaGetSymbolAddress((void**)&xh_i, g_xh_i);
    cudaGetSymbolAddress((void**)&h1h_u, g_h1h_u);
    cudaGetSymbolAddress((void**)&h1h_i, g_h1h_i);
    cudaGetSymbolAddress((void**)&mh_u, g_mh_u);
    cudaGetSymbolAddress((void**)&mh_i, g_mh_i);
    cudaGetSymbolAddress((void**)&deg_u, g_deg_u);
    cudaGetSymbolAddress((void**)&deg_i, g_deg_i);
    cudaGetSymbolAddress((void**)&off_u, g_off_u);
    cudaGetSymbolAddress((void**)&off_i, g_off_i);
    cudaGetSymbolAddress((void**)&cur_u, g_cur_u);
    cudaGetSymbolAddress((void**)&cur_i, g_cur_i);
    cudaGetSymbolAddress((void**)&adj_u, g_adj_u);
    cudaGetSymbolAddress((void**)&adj_i, g_adj_i);
    cudaGetSymbolAddress((void**)&bsum, g_bsum);
    cudaGetSymbolAddress((void**)&wtb, g_wtb);

    cudaFuncSetAttribute(sage_gemm2, cudaFuncAttributeMaxDynamicSharedMemorySize,
                         SM_BYTES);

    float* out_u = (float*)d_out;
    float* out_i = out_u + (size_t)NU * DD;

    // weight prep (fp16 block layout; one launch)
    prep_weights4<<<128, 256>>>(W1r_iu, L1W_u, W1l_iu,
                                W1r_ui, L1W_i, W1l_ui,
                                W2r_iu, L2W_u, W2l_iu,
                                W2r_ui, L2W_i, W2l_ui, wtb);

    // fp16 copies of input features
    {
        int nA = NU * DD, nB = NI * DD;
        int thr = (nA + nB) / 8;
        conv_fp16_2<<<(thr + 255) / 256, 256>>>(x_user, xh_u, nA, x_item, xh_i, nB);
    }

    // CSR build (once; shared by both layers)
    cudaMemsetAsync(deg_u, 0, NU * sizeof(int));
    cudaMemsetAsync(deg_i, 0, NI * sizeof(int));
    count_deg<<<(2 * E + 255) / 256, 256>>>(iu_dst, ui_dst, E, deg_u, deg_i);
    int nbU = (NU + SCAN_B - 1) / SCAN_B, nbI = (NI + SCAN_B - 1) / SCAN_B;
    scan_part<<<nbU + nbI, SCAN_B>>>(deg_u, NU, deg_i, NI, off_u, off_i, bsum, nbU);
    scan_top<<<1, 256>>>(bsum, nbU, nbI, off_u, NU, off_i, NI);
    scan_add<<<(NU + NI + 255) / 256, 256>>>(off_u, cur_u, NU, off_i, cur_i, NI, bsum, nbU);
    fill_adj<<<(2 * E + 255) / 256, 256>>>(iu_src, iu_dst, ui_src, ui_dst, E,
                                           cur_u, adj_u, cur_i, adj_i);

    int gblocks = ((NU + NI) * 32 + 255) / 256;
    // layer 1 aggregation: fp16 mean (scaling folded in)
    gather_mean2<<<gblocks, 256>>>(xh_i, adj_u, off_u, mh_u, NU,
                                   xh_u, adj_i, off_i, mh_i, NI);

    int gu = (NU + 127) / 128, gi = (NI + 127) / 128;
    // layer 1 GEMMs (merged; fp16 h1 output)
    sage_gemm2<<<gu + gi, 512, SM_BYTES>>>(
        xh_u, mh_u, wtb + 0 * 32768, b1_iu, L1b_u, (float*)0, h1h_u, NU, gu,
        xh_i, mh_i, wtb + 1 * 32768, b1_ui, L1b_i, (float*)0, h1h_i, NI, 1);

    // layer 2 aggregation
    gather_mean2<<<gblocks, 256>>>(h1h_i, adj_u, off_u, mh_u, NU,
                                   h1h_u, adj_i, off_i, mh_i, NI);

    // layer 2 GEMMs (merged; fp32 output)
    sage_gemm2<<<gu + gi, 512, SM_BYTES>>>(
        h1h_u, mh_u, wtb + 2 * 32768, b2_iu, L2b_u, out_u, (__half*)0, NU, gu,
        h1h_i, mh_i, wtb + 3 * 32768, b2_ui, L2b_i, out_i, (__half*)0, NI, 0);
}